// round 16
// baseline (speedup 1.0000x reference)
#include <cuda_runtime.h>
#include <math.h>

#define B 16
#define L 128
#define H 1024
#define V 50257
#define T (L-1)
#define BP (B/2)
#define NQ 12563             // quads per row; 4*NQ = 50252
#define NB123 296            // fused front kernel: exactly 2 CTAs/SM x 148

typedef unsigned long long u64;

// ---- scratch (no allocations allowed) ----
__device__ float g_x0[B * H];
__device__ float g_h0[B * H];
__device__ float g_gi[B * 3 * H];
__device__ float g_gh[B * 3 * H];
__device__ float g_h1[B * H];
__device__ float g_logits[(size_t)B * V];
__device__ float g_sum[B];

// grid barrier state (generation counter -> graph-replay safe)
__device__ volatile unsigned g_bar_gen;
__device__ unsigned g_bar_cnt;

__device__ __forceinline__ void grid_barrier(int nblocks) {
    __syncthreads();
    if (threadIdx.x == 0) {
        unsigned gen = g_bar_gen;
        __threadfence();
        if (atomicAdd(&g_bar_cnt, 1) == (unsigned)(nblocks - 1)) {
            g_bar_cnt = 0;
            __threadfence();
            g_bar_gen = gen + 1;
        } else {
            while (g_bar_gen == gen) { }
        }
    }
    __syncthreads();
}

// packed f32x2 FMA: d = a*b + d (2 MACs / SASS FFMA2)
__device__ __forceinline__ void ffma2(u64 &d, u64 a, u64 b) {
    asm("fma.rn.f32x2 %0, %1, %2, %0;" : "+l"(d) : "l"(a), "l"(b));
}
__device__ __forceinline__ u64 dup2(float f) {
    u64 r;
    asm("mov.b64 %0, {%1, %1};" : "=l"(r) : "f"(f));
    return r;
}
__device__ __forceinline__ float lo2(u64 a) { return __uint_as_float((unsigned)a); }
__device__ __forceinline__ float hi2(u64 a) { return __uint_as_float((unsigned)(a >> 32)); }

// XOR swizzle on u64 index: flips the 16B-granule bit on alternating 128B lines
__device__ __forceinline__ int swz(int i) { return i ^ (((i >> 4) & 1) << 1); }

// cp.async 16B, L2-only path (streaming)
__device__ __forceinline__ void cpasync16(unsigned dst, const void* src) {
    asm volatile("cp.async.cg.shared.global [%0], [%1], 16;" :: "r"(dst), "l"(src) : "memory");
}
__device__ __forceinline__ void cpcommit() {
    asm volatile("cp.async.commit_group;" ::: "memory");
}
template <int N>
__device__ __forceinline__ void cpwait() {
    asm volatile("cp.async.wait_group %0;" :: "n"(N) : "memory");
}

// ---------------------------------------------------------------------------
// K123: fused embed+bridge (float4, re-tiled) -> barrier -> gates GEMV (with
// weight prefetch) -> barrier -> GRU cell. Zeroes g_sum for k4's atomics.
//
// Phase A tiling: quad = (b, h4) float4 column (4096 total), 16 l-chunks of
// 8. Block bi<256 owns quads [16bi,16bi+16): thread (chunk=tid>>4,
// quadL=tid&15) loads 8 float4 (256B-contiguous per warp), partials reduced
// through smem (conflict-free: reducer tid reads addrs == tid mod 32).
// ---------------------------------------------------------------------------
__global__ __launch_bounds__(256, 2)
void k123_front(const int* __restrict__ input,
                const float* __restrict__ hidden,
                const float* __restrict__ emb,
                const float* __restrict__ bridge_w,
                const float* __restrict__ bridge_b,
                const float* __restrict__ w_ih,
                const float* __restrict__ w_hh,
                const float* __restrict__ b_ih,
                const float* __restrict__ b_hh) {
    __shared__ float bw[L];
    __shared__ float4 spart[16][16];      // [chunk][quadL]
    int tid = threadIdx.x;
    if (tid < L) bw[tid] = bridge_w[tid];
    if (blockIdx.x == 0 && tid < B) g_sum[tid] = 0.f;
    __syncthreads();

    // ---- phase A: h0 = bridge(hidden) + bb ; x0 = relu(emb[tok]) ----
    if (blockIdx.x < 256) {
        int quadL = tid & 15;
        int chunk = tid >> 4;
        int quad  = blockIdx.x * 16 + quadL;   // 0..4095
        int b  = quad >> 8;
        int h4 = quad & 255;
        const float4* hp = (const float4*)(hidden + (size_t)b * L * H
                                           + (size_t)(chunk * 8) * H) + h4;
        float4 acc = make_float4(0.f, 0.f, 0.f, 0.f);
        #pragma unroll
        for (int i = 0; i < 8; i++) {
            float4 v = __ldcs(hp + i * (H / 4));
            float w = bw[chunk * 8 + i];
            acc.x += v.x * w; acc.y += v.y * w;
            acc.z += v.z * w; acc.w += v.w * w;
        }
        spart[chunk][quadL] = acc;
        __syncthreads();

        if (tid < 64) {
            int qL = tid >> 2, comp = tid & 3;
            const float* sp = (const float*)&spart[0][0];
            float s = 0.f;
            #pragma unroll
            for (int c = 0; c < 16; c++) s += sp[c * 64 + qL * 4 + comp];
            int q = blockIdx.x * 16 + qL;
            g_h0[q * 4 + comp] = s + bridge_b[0];
        }
        if (tid < 16) {
            int q = blockIdx.x * 16 + tid;
            int b2 = q >> 8, h42 = q & 255;
            int tok = input[b2 * L];
            float4 e = *((const float4*)(emb + (size_t)tok * H) + h42);
            e.x = fmaxf(e.x, 0.f); e.y = fmaxf(e.y, 0.f);
            e.z = fmaxf(e.z, 0.f); e.w = fmaxf(e.w, 0.f);
            ((float4*)g_x0)[q] = e;
        }
    }

    grid_barrier(NB123);

    // ---- phase B: gi = x0 @ w_ih^T + b_ih ; gh = h0 @ w_hh^T + b_hh ----
    {
        int warp = tid >> 5;
        int lane = tid & 31;
        int j0 = (blockIdx.x * 8 + warp) * 2;
        if (j0 < 3 * H) {
            float ai0[B], ai1[B], ah0[B], ah1[B];
            #pragma unroll
            for (int b = 0; b < B; b++) { ai0[b] = ai1[b] = ah0[b] = ah1[b] = 0.f; }

            const float* pwi0 = w_ih + (size_t)(j0 + 0) * H;
            const float* pwi1 = w_ih + (size_t)(j0 + 1) * H;
            const float* pwh0 = w_hh + (size_t)(j0 + 0) * H;
            const float* pwh1 = w_hh + (size_t)(j0 + 1) * H;

            int k = lane * 4;
            float4 wi0 = *(const float4*)(pwi0 + k);
            float4 wi1 = *(const float4*)(pwi1 + k);
            float4 wh0 = *(const float4*)(pwh0 + k);
            float4 wh1 = *(const float4*)(pwh1 + k);

            #pragma unroll
            for (int i = 0; i < 8; i++) {
                float4 cwi0 = wi0, cwi1 = wi1, cwh0 = wh0, cwh1 = wh1;
                int kc = i * 128 + lane * 4;
                if (i < 7) {
                    int kn = kc + 128;
                    wi0 = *(const float4*)(pwi0 + kn);
                    wi1 = *(const float4*)(pwi1 + kn);
                    wh0 = *(const float4*)(pwh0 + kn);
                    wh1 = *(const float4*)(pwh1 + kn);
                }
                #pragma unroll
                for (int b = 0; b < B; b++) {
                    float4 x = *(const float4*)(g_x0 + b * H + kc);
                    float4 h = *(const float4*)(g_h0 + b * H + kc);
                    ai0[b] += cwi0.x * x.x + cwi0.y * x.y + cwi0.z * x.z + cwi0.w * x.w;
                    ai1[b] += cwi1.x * x.x + cwi1.y * x.y + cwi1.z * x.z + cwi1.w * x.w;
                    ah0[b] += cwh0.x * h.x + cwh0.y * h.y + cwh0.z * h.z + cwh0.w * h.w;
                    ah1[b] += cwh1.x * h.x + cwh1.y * h.y + cwh1.z * h.z + cwh1.w * h.w;
                }
            }

            #pragma unroll
            for (int b = 0; b < B; b++) {
                #pragma unroll
                for (int o = 16; o; o >>= 1) {
                    ai0[b] += __shfl_xor_sync(0xffffffffu, ai0[b], o);
                    ai1[b] += __shfl_xor_sync(0xffffffffu, ai1[b], o);
                    ah0[b] += __shfl_xor_sync(0xffffffffu, ah0[b], o);
                    ah1[b] += __shfl_xor_sync(0xffffffffu, ah1[b], o);
                }
            }

            if (lane == 0) {
                float bi0 = b_ih[j0], bi1 = b_ih[j0 + 1];
                float bh0 = b_hh[j0], bh1 = b_hh[j0 + 1];
                #pragma unroll
                for (int b = 0; b < B; b++) {
                    g_gi[b * 3 * H + j0]     = ai0[b] + bi0;
                    g_gi[b * 3 * H + j0 + 1] = ai1[b] + bi1;
                    g_gh[b * 3 * H + j0]     = ah0[b] + bh0;
                    g_gh[b * 3 * H + j0 + 1] = ah1[b] + bh1;
                }
            }
        }
    }

    grid_barrier(NB123);

    // ---- phase C: GRU cell -> h1 ----
    {
        int gtid = blockIdx.x * 256 + tid;
        if (gtid < B * H) {
            int b = gtid >> 10;
            int h = gtid & (H - 1);
            int base = b * 3 * H + h;
            float ir = g_gi[base], iz = g_gi[base + H], in_ = g_gi[base + 2 * H];
            float hr = g_gh[base], hz = g_gh[base + H], hn  = g_gh[base + 2 * H];
            float r = 1.f / (1.f + expf(-(ir + hr)));
            float z = 1.f / (1.f + expf(-(iz + hz)));
            float n = tanhf(in_ + r * hn);
            g_h1[gtid] = (1.f - z) * n + z * g_h0[gtid];
        }
    }
}

// ---------------------------------------------------------------------------
// K4: logits[b,v] = h1[b,:] . proj_w[v,:] + proj_b[v]  +  fused exp-sum.
// (committed version, unchanged)
// ---------------------------------------------------------------------------
__global__ __launch_bounds__(256, 2)
void k4_proj(const float* __restrict__ proj_w,
             const float* __restrict__ proj_b) {
    __shared__ float sbin[B];
    __shared__ float wbuf[8][64];
    extern __shared__ char smem_raw[];
    u64*  hs = (u64*)smem_raw;                    // 64KB, swizzled
    char* pf = smem_raw + 65536;                  // 32KB staging

    int tid  = threadIdx.x;
    if (tid < B) sbin[tid] = 0.f;
    for (int i = tid; i < BP * H; i += 256) {
        int bp = i >> 10;
        int k  = i & (H - 1);
        unsigned lo = __float_as_uint(g_h1[(2 * bp) * H + k]);
        unsigned hi = __float_as_uint(g_h1[(2 * bp + 1) * H + k]);
        hs[swz(i)] = ((u64)hi << 32) | (u64)lo;
    }
    __syncthreads();

    int warp = tid >> 5;
    int lane = tid & 31;
    int v0 = (blockIdx.x * 8 + warp) * 4;

    if (v0 < V) {
        int r1 = min(v0 + 1, V - 1);
        int r2 = min(v0 + 2, V - 1);
        int r3 = min(v0 + 3, V - 1);
        const char* w0 = (const char*)(proj_w + (size_t)v0 * H);
        const char* w1 = (const char*)(proj_w + (size_t)r1 * H);
        const char* w2 = (const char*)(proj_w + (size_t)r2 * H);
        const char* w3 = (const char*)(proj_w + (size_t)r3 * H);

        char* pfw = pf + warp * 4096 + lane * 16;
        unsigned pfw_s = (unsigned)__cvta_generic_to_shared(pfw);

        u64 a0[BP], a1[BP], a2[BP], a3[BP];
        #pragma unroll
        for (int bp = 0; bp < BP; bp++) { a0[bp] = a1[bp] = a2[bp] = a3[bp] = 0ull; }

        {
            int off = lane * 16;
            cpasync16(pfw_s + 0 * 2048 + 0 * 512, w0 + off);
            cpasync16(pfw_s + 0 * 2048 + 1 * 512, w1 + off);
            cpasync16(pfw_s + 0 * 2048 + 2 * 512, w2 + off);
            cpasync16(pfw_s + 0 * 2048 + 3 * 512, w3 + off);
            cpcommit();
            cpasync16(pfw_s + 1 * 2048 + 0 * 512, w0 + 512 + off);
            cpasync16(pfw_s + 1 * 2048 + 1 * 512, w1 + 512 + off);
            cpasync16(pfw_s + 1 * 2048 + 2 * 512, w2 + 512 + off);
            cpasync16(pfw_s + 1 * 2048 + 3 * 512, w3 + 512 + off);
            cpcommit();
        }

        #pragma unroll
        for (int i = 0; i < 8; i++) {
            const int buf = i & 1;
            if (i < 6) cpwait<1>(); else cpwait<0>();

            const char* pb = pf + warp * 4096 + buf * 2048 + lane * 16;
            float4 p0 = *(const float4*)(pb + 0 * 512);
            float4 p1 = *(const float4*)(pb + 1 * 512);
            float4 p2 = *(const float4*)(pb + 2 * 512);
            float4 p3 = *(const float4*)(pb + 3 * 512);
            u64 q0x = dup2(p0.x), q0y = dup2(p0.y), q0z = dup2(p0.z), q0w = dup2(p0.w);
            u64 q1x = dup2(p1.x), q1y = dup2(p1.y), q1z = dup2(p1.z), q1w = dup2(p1.w);
            u64 q2x = dup2(p2.x), q2y = dup2(p2.y), q2z = dup2(p2.z), q2w = dup2(p2.w);
            u64 q3x = dup2(p3.x), q3y = dup2(p3.y), q3z = dup2(p3.z), q3w = dup2(p3.w);

            if (i < 6) {
                int off = (i + 2) * 512 + lane * 16;
                unsigned d = pfw_s + buf * 2048;
                cpasync16(d + 0 * 512, w0 + off);
                cpasync16(d + 1 * 512, w1 + off);
                cpasync16(d + 2 * 512, w2 + off);
                cpasync16(d + 3 * 512, w3 + off);
                cpcommit();
            }

            int kq = i * 32 + lane;
            #pragma unroll
            for (int bp = 0; bp < BP; bp++) {
                int idx = bp * 1024 + kq * 4;
                int f   = ((idx >> 4) & 1) << 1;
                ulonglong2 xa = *(const ulonglong2*)(hs + (idx ^ f));
                ulonglong2 xb = *(const ulonglong2*)(hs + ((idx + 2) ^ f));
                ffma2(a0[bp], q0x, xa.x); ffma2(a0[bp], q0y, xa.y);
                ffma2(a0[bp], q0z, xb.x); ffma2(a0[bp], q0w, xb.y);
                ffma2(a1[bp], q1x, xa.x); ffma2(a1[bp], q1y, xa.y);
                ffma2(a1[bp], q1z, xb.x); ffma2(a1[bp], q1w, xb.y);
                ffma2(a2[bp], q2x, xa.x); ffma2(a2[bp], q2y, xa.y);
                ffma2(a2[bp], q2z, xb.x); ffma2(a2[bp], q2w, xb.y);
                ffma2(a3[bp], q3x, xa.x); ffma2(a3[bp], q3y, xa.y);
                ffma2(a3[bp], q3z, xb.x); ffma2(a3[bp], q3w, xb.y);
            }
        }

        float pb0 = proj_b[v0];
        float pb1 = proj_b[r1];
        float pb2 = proj_b[r2];
        float pb3 = proj_b[r3];
        bool val1 = (v0 + 1 < V), val2 = (v0 + 2 < V), val3 = (v0 + 3 < V);

        #pragma unroll
        for (int bp = 0; bp < BP; bp++) {
            float s0a = lo2(a0[bp]), s0b = hi2(a0[bp]);
            float s1a = lo2(a1[bp]), s1b = hi2(a1[bp]);
            float s2a = lo2(a2[bp]), s2b = hi2(a2[bp]);
            float s3a = lo2(a3[bp]), s3b = hi2(a3[bp]);
            #pragma unroll
            for (int o = 16; o; o >>= 1) {
                s0a += __shfl_xor_sync(0xffffffffu, s0a, o);
                s0b += __shfl_xor_sync(0xffffffffu, s0b, o);
                s1a += __shfl_xor_sync(0xffffffffu, s1a, o);
                s1b += __shfl_xor_sync(0xffffffffu, s1b, o);
                s2a += __shfl_xor_sync(0xffffffffu, s2a, o);
                s2b += __shfl_xor_sync(0xffffffffu, s2b, o);
                s3a += __shfl_xor_sync(0xffffffffu, s3a, o);
                s3b += __shfl_xor_sync(0xffffffffu, s3b, o);
            }
            if (lane == 0) {
                float* lga = g_logits + (size_t)(2 * bp) * V;
                float* lgb = g_logits + (size_t)(2 * bp + 1) * V;
                lga[v0] = s0a + pb0;  lgb[v0] = s0b + pb0;
                if (val1) { lga[v0 + 1] = s1a + pb1;  lgb[v0 + 1] = s1b + pb1; }
                if (val2) { lga[v0 + 2] = s2a + pb2;  lgb[v0 + 2] = s2b + pb2; }
                if (val3) { lga[v0 + 3] = s3a + pb3;  lgb[v0 + 3] = s3b + pb3; }
                wbuf[warp][bp * 8 + 0] = s0a + pb0;
                wbuf[warp][bp * 8 + 1] = s0b + pb0;
                wbuf[warp][bp * 8 + 2] = val1 ? s1a + pb1 : -1e30f;
                wbuf[warp][bp * 8 + 3] = val1 ? s1b + pb1 : -1e30f;
                wbuf[warp][bp * 8 + 4] = val2 ? s2a + pb2 : -1e30f;
                wbuf[warp][bp * 8 + 5] = val2 ? s2b + pb2 : -1e30f;
                wbuf[warp][bp * 8 + 6] = val3 ? s3a + pb3 : -1e30f;
                wbuf[warp][bp * 8 + 7] = val3 ? s3b + pb3 : -1e30f;
            }
        }
        __syncwarp();
        if (lane < B) {
            int bp = lane >> 1, half = lane & 1;
            float e = (expf(wbuf[warp][bp * 8 + 0 + half]) +
                       expf(wbuf[warp][bp * 8 + 2 + half])) +
                      (expf(wbuf[warp][bp * 8 + 4 + half]) +
                       expf(wbuf[warp][bp * 8 + 6 + half]));
            atomicAdd(&sbin[lane], e);
        }
    }

    __syncthreads();
    if (tid < B) atomicAdd(&g_sum[tid], sbin[tid]);
}

// ---------------------------------------------------------------------------
// K6: out[b,t,v] = logits[b,v] - log(g_sum[b]), aligned STG.128 quads,
// streaming stores. (committed version, unchanged)
// ---------------------------------------------------------------------------
__global__ void k6_out(float* __restrict__ out) {
    int j = blockIdx.x * 256 + threadIdx.x;
    int b = blockIdx.y;
    if (j > NQ) return;
    float sub = logf(g_sum[b]);
    const float* lg = g_logits + (size_t)b * V;
    float* ob = out + (size_t)b * T * V;

    if (j < NQ) {
        float q0 = lg[4 * j + 0] - sub, q1 = lg[4 * j + 1] - sub;
        float q2 = lg[4 * j + 2] - sub, q3 = lg[4 * j + 3] - sub;
        float q4 = lg[4 * j + 4] - sub, q5 = lg[4 * j + 5] - sub;
        float q6 = lg[4 * j + 6] - sub;
        float4 v0 = make_float4(q0, q1, q2, q3);   // s=0 (r%4==0)
        float4 v3 = make_float4(q3, q4, q5, q6);   // s=3 (r%4==1)
        float4 v2 = make_float4(q2, q3, q4, q5);   // s=2 (r%4==2)
        float4 v1 = make_float4(q1, q2, q3, q4);   // s=1 (r%4==3)

        // r = b*127 + t ≡ 3b + t (mod 4); r≡c ⇔ t ≡ c + b (mod 4)
        int t0;
        t0 = (0 + b) & 3;
        #pragma unroll 4
        for (int t = t0; t < T; t += 4) __stcs((float4*)(ob + (size_t)t * V + 4 * j + 0), v0);
        t0 = (1 + b) & 3;
        #pragma unroll 4
        for (int t = t0; t < T; t += 4) __stcs((float4*)(ob + (size_t)t * V + 4 * j + 3), v3);
        t0 = (2 + b) & 3;
        #pragma unroll 4
        for (int t = t0; t < T; t += 4) __stcs((float4*)(ob + (size_t)t * V + 4 * j + 2), v2);
        t0 = (3 + b) & 3;
        #pragma unroll 4
        for (int t = t0; t < T; t += 4) __stcs((float4*)(ob + (size_t)t * V + 4 * j + 1), v1);
    } else {
        float h0 = lg[0] - sub, h1 = lg[1] - sub, h2 = lg[2] - sub;
        float e0 = lg[4 * NQ + 0] - sub, e1 = lg[4 * NQ + 1] - sub;
        float e2 = lg[4 * NQ + 2] - sub, e3 = lg[4 * NQ + 3] - sub;
        float e4 = lg[4 * NQ + 4] - sub;
        for (int t = 0; t < T; t++) {
            int c = (3 * b + t) & 3;        // r & 3
            int sshift = (4 - c) & 3;
            float* row = ob + (size_t)t * V;
            if (sshift > 0) __stcs(row + 0, h0);
            if (sshift > 1) __stcs(row + 1, h1);
            if (sshift > 2) __stcs(row + 2, h2);
            if (sshift == 0) __stcs(row + 4 * NQ + 0, e0);
            if (sshift <= 1) __stcs(row + 4 * NQ + 1, e1);
            if (sshift <= 2) __stcs(row + 4 * NQ + 2, e2);
            if (sshift <= 3) __stcs(row + 4 * NQ + 3, e3);
            __stcs(row + 4 * NQ + 4, e4);
        }
    }
}

// ---------------------------------------------------------------------------
extern "C" void kernel_launch(void* const* d_in, const int* in_sizes, int n_in,
                              void* d_out, int out_size) {
    const int*   input    = (const int*)d_in[0];
    const float* hidden   = (const float*)d_in[1];
    const float* emb      = (const float*)d_in[2];
    const float* bridge_w = (const float*)d_in[3];
    const float* bridge_b = (const float*)d_in[4];
    const float* w_ih     = (const float*)d_in[5];
    const float* w_hh     = (const float*)d_in[6];
    const float* b_ih     = (const float*)d_in[7];
    const float* b_hh     = (const float*)d_in[8];
    const float* proj_w   = (const float*)d_in[9];
    const float* proj_b   = (const float*)d_in[10];
    float* out = (float*)d_out;

    const int k4_smem = 65536 + 32768;
    cudaFuncSetAttribute(k4_proj, cudaFuncAttributeMaxDynamicSharedMemorySize,
                         k4_smem);

    k123_front<<<NB123, 256>>>(input, hidden, emb, bridge_w, bridge_b,
                               w_ih, w_hh, b_ih, b_hh);
    int blocks4 = (V + 31) / 32;
    k4_proj<<<blocks4, 256, k4_smem>>>(proj_w, proj_b);
    dim3 g6(50, B);
    k6_out<<<g6, 256>>>(out);
}

// round 17
// speedup vs baseline: 1.1200x; 1.1200x over previous
#include <cuda_runtime.h>
#include <math.h>

#define B 16
#define L 128
#define H 1024
#define V 50257
#define T (L-1)
#define NQ 12563             // quads per row; 4*NQ = 50252
#define NB123 296            // fused front kernel: exactly 2 CTAs/SM x 148
#define VPB 128              // vocab rows per k4 block (16 warps x 8)
#define NB4 ((V + VPB - 1) / VPB)   // 393

typedef unsigned long long u64;
typedef unsigned int u32;

// ---- scratch (no allocations allowed) ----
__device__ float g_x0[B * H];
__device__ float g_h0[B * H];
__device__ float g_gi[B * 3 * H];
__device__ float g_gh[B * 3 * H];
__device__ float g_h1[B * H];
__device__ float g_logits[(size_t)B * V];
__device__ float g_sum[B];

// grid barrier state (generation counter -> graph-replay safe)
__device__ volatile unsigned g_bar_gen;
__device__ unsigned g_bar_cnt;

__device__ __forceinline__ void grid_barrier(int nblocks) {
    __syncthreads();
    if (threadIdx.x == 0) {
        unsigned gen = g_bar_gen;
        __threadfence();
        if (atomicAdd(&g_bar_cnt, 1) == (unsigned)(nblocks - 1)) {
            g_bar_cnt = 0;
            __threadfence();
            g_bar_gen = gen + 1;
        } else {
            while (g_bar_gen == gen) { }
        }
    }
    __syncthreads();
}

// tf32 warp MMA: D(16x8) += A(16x8) x B(8x8). fp32 bits fed raw (HW truncates).
__device__ __forceinline__ void mma_tf32(float &d0, float &d1, float &d2, float &d3,
                                         u32 a0, u32 a1, u32 a2, u32 a3,
                                         u32 b0, u32 b1) {
    asm volatile(
        "mma.sync.aligned.m16n8k8.row.col.f32.tf32.tf32.f32 "
        "{%0,%1,%2,%3}, {%4,%5,%6,%7}, {%8,%9}, {%0,%1,%2,%3};"
        : "+f"(d0), "+f"(d1), "+f"(d2), "+f"(d3)
        : "r"(a0), "r"(a1), "r"(a2), "r"(a3), "r"(b0), "r"(b1));
}

// cp.async 16B, L2-only path (streaming)
__device__ __forceinline__ void cpasync16(unsigned dst, const void* src) {
    asm volatile("cp.async.cg.shared.global [%0], [%1], 16;" :: "r"(dst), "l"(src) : "memory");
}
__device__ __forceinline__ void cpcommit() {
    asm volatile("cp.async.commit_group;" ::: "memory");
}
template <int N>
__device__ __forceinline__ void cpwait() {
    asm volatile("cp.async.wait_group %0;" :: "n"(N) : "memory");
}

// ---------------------------------------------------------------------------
// K123: fused embed+bridge -> barrier -> gates GEMV (weight prefetch) ->
// barrier -> GRU cell. (round-15 committed version, unchanged)
// ---------------------------------------------------------------------------
__global__ __launch_bounds__(256, 2)
void k123_front(const int* __restrict__ input,
                const float* __restrict__ hidden,
                const float* __restrict__ emb,
                const float* __restrict__ bridge_w,
                const float* __restrict__ bridge_b,
                const float* __restrict__ w_ih,
                const float* __restrict__ w_hh,
                const float* __restrict__ b_ih,
                const float* __restrict__ b_hh) {
    __shared__ float bw[L];
    __shared__ float part[4][64];
    int tid = threadIdx.x;
    if (tid < L) bw[tid] = bridge_w[tid];
    if (blockIdx.x == 0 && tid < B) g_sum[tid] = 0.f;
    __syncthreads();

    // ---- phase A ----
    int slot = tid & 63;
    int lc   = tid >> 6;
    int i0 = blockIdx.x * 64;
    if (i0 < B * H) {
        int i = i0 + slot;
        int b = i >> 10;
        int h = i & (H - 1);
        const float* hp = hidden + (size_t)b * L * H + (size_t)(lc * 32) * H + h;
        float a0 = 0.f, a1 = 0.f, a2 = 0.f, a3 = 0.f;
        #pragma unroll
        for (int l = 0; l < 32; l += 4) {
            a0 += __ldcs(hp + (l + 0) * H) * bw[lc * 32 + l + 0];
            a1 += __ldcs(hp + (l + 1) * H) * bw[lc * 32 + l + 1];
            a2 += __ldcs(hp + (l + 2) * H) * bw[lc * 32 + l + 2];
            a3 += __ldcs(hp + (l + 3) * H) * bw[lc * 32 + l + 3];
        }
        part[lc][slot] = (a0 + a1) + (a2 + a3);
        __syncthreads();
        if (lc == 0) {
            int tok = input[b * L];
            g_x0[i] = fmaxf(emb[(size_t)tok * H + h], 0.0f);
            g_h0[i] = (part[0][slot] + part[1][slot]) +
                      (part[2][slot] + part[3][slot]) + bridge_b[0];
        }
    }

    grid_barrier(NB123);

    // ---- phase B ----
    {
        int warp = tid >> 5;
        int lane = tid & 31;
        int j0 = (blockIdx.x * 8 + warp) * 2;
        if (j0 < 3 * H) {
            float ai0[B], ai1[B], ah0[B], ah1[B];
            #pragma unroll
            for (int b = 0; b < B; b++) { ai0[b] = ai1[b] = ah0[b] = ah1[b] = 0.f; }

            const float* pwi0 = w_ih + (size_t)(j0 + 0) * H;
            const float* pwi1 = w_ih + (size_t)(j0 + 1) * H;
            const float* pwh0 = w_hh + (size_t)(j0 + 0) * H;
            const float* pwh1 = w_hh + (size_t)(j0 + 1) * H;

            int k = lane * 4;
            float4 wi0 = *(const float4*)(pwi0 + k);
            float4 wi1 = *(const float4*)(pwi1 + k);
            float4 wh0 = *(const float4*)(pwh0 + k);
            float4 wh1 = *(const float4*)(pwh1 + k);

            #pragma unroll
            for (int i = 0; i < 8; i++) {
                float4 cwi0 = wi0, cwi1 = wi1, cwh0 = wh0, cwh1 = wh1;
                int kc = i * 128 + lane * 4;
                if (i < 7) {
                    int kn = kc + 128;
                    wi0 = *(const float4*)(pwi0 + kn);
                    wi1 = *(const float4*)(pwi1 + kn);
                    wh0 = *(const float4*)(pwh0 + kn);
                    wh1 = *(const float4*)(pwh1 + kn);
                }
                #pragma unroll
                for (int b = 0; b < B; b++) {
                    float4 x = *(const float4*)(g_x0 + b * H + kc);
                    float4 h = *(const float4*)(g_h0 + b * H + kc);
                    ai0[b] += cwi0.x * x.x + cwi0.y * x.y + cwi0.z * x.z + cwi0.w * x.w;
                    ai1[b] += cwi1.x * x.x + cwi1.y * x.y + cwi1.z * x.z + cwi1.w * x.w;
                    ah0[b] += cwh0.x * h.x + cwh0.y * h.y + cwh0.z * h.z + cwh0.w * h.w;
                    ah1[b] += cwh1.x * h.x + cwh1.y * h.y + cwh1.z * h.z + cwh1.w * h.w;
                }
            }

            #pragma unroll
            for (int b = 0; b < B; b++) {
                #pragma unroll
                for (int o = 16; o; o >>= 1) {
                    ai0[b] += __shfl_xor_sync(0xffffffffu, ai0[b], o);
                    ai1[b] += __shfl_xor_sync(0xffffffffu, ai1[b], o);
                    ah0[b] += __shfl_xor_sync(0xffffffffu, ah0[b], o);
                    ah1[b] += __shfl_xor_sync(0xffffffffu, ah1[b], o);
                }
            }

            if (lane == 0) {
                float bi0 = b_ih[j0], bi1 = b_ih[j0 + 1];
                float bh0 = b_hh[j0], bh1 = b_hh[j0 + 1];
                #pragma unroll
                for (int b = 0; b < B; b++) {
                    g_gi[b * 3 * H + j0]     = ai0[b] + bi0;
                    g_gi[b * 3 * H + j0 + 1] = ai1[b] + bi1;
                    g_gh[b * 3 * H + j0]     = ah0[b] + bh0;
                    g_gh[b * 3 * H + j0 + 1] = ah1[b] + bh1;
                }
            }
        }
    }

    grid_barrier(NB123);

    // ---- phase C ----
    {
        int gtid = blockIdx.x * 256 + tid;
        if (gtid < B * H) {
            int b = gtid >> 10;
            int h = gtid & (H - 1);
            int base = b * 3 * H + h;
            float ir = g_gi[base], iz = g_gi[base + H], in_ = g_gi[base + 2 * H];
            float hr = g_gh[base], hz = g_gh[base + H], hn  = g_gh[base + 2 * H];
            float r = 1.f / (1.f + expf(-(ir + hr)));
            float z = 1.f / (1.f + expf(-(iz + hz)));
            float n = tanhf(in_ + r * hn);
            g_h1[gtid] = (1.f - z) * n + z * g_h0[gtid];
        }
    }
}

// ---------------------------------------------------------------------------
// K4: logits = h1 @ proj_w^T + proj_b via tf32 mma.sync.m16n8k8 (M=16=batch,
// zero padding waste). Per warp: 8 vocab rows, D = 4 fp32 regs.
//  - A (h1) packed ONCE into fragment order: afrag[s][lane] = float4
//    {h1[g][8s+t], h1[g+8][8s+t], h1[g][8s+t+4], h1[g+8][8s+t+4]},
//    g=lane>>2, t=lane&3 -> one conflict-free LDS.128 per mma.
//  - B (proj_w) cp.async double-buffered, row stride 132 floats ->
//    bank = (lane + 8s) % 32, conflict-free.
//  - Two accumulator sets (even/odd slice) for mma ILP.
// Fused exp-sum epilogue (quad shfl-reduce -> smem bins -> global atomics).
// ---------------------------------------------------------------------------
__global__ __launch_bounds__(512, 1)
void k4_proj(const float* __restrict__ proj_w,
             const float* __restrict__ proj_b) {
    __shared__ float sbin[B];
    extern __shared__ char smem_raw[];
    float* afrag = (float*)smem_raw;               // 128*32*4 floats = 64KB
    // staging: per warp 2 bufs x 8 rows x 132 floats (528B rows)
    char*  wsbase = smem_raw + 65536;              // 16 warps * 8448B = 132KB

    int tid  = threadIdx.x;
    int warp = tid >> 5;
    int lane = tid & 31;
    if (tid < B) sbin[tid] = 0.f;

    // build A fragments from g_h1
    for (int idx = tid; idx < 128 * 32; idx += 512) {
        int s  = idx >> 5;
        int ln = idx & 31;
        int g  = ln >> 2;
        int t  = ln & 3;
        int k  = s * 8 + t;
        float4 v;
        v.x = g_h1[g * H + k];
        v.y = g_h1[(g + 8) * H + k];
        v.z = g_h1[g * H + k + 4];
        v.w = g_h1[(g + 8) * H + k + 4];
        ((float4*)afrag)[idx] = v;
    }
    __syncthreads();

    int v0 = blockIdx.x * VPB + warp * 8;      // this warp's 8 vocab rows
    int vr[8];
    #pragma unroll
    for (int r = 0; r < 8; r++) vr[r] = min(v0 + r, V - 1);

    char* ws = wsbase + warp * 8448;           // this warp's staging
    unsigned ws_s = (unsigned)__cvta_generic_to_shared(ws);

    float da0 = 0.f, da1 = 0.f, da2 = 0.f, da3 = 0.f;
    float db0 = 0.f, db1 = 0.f, db2 = 0.f, db3 = 0.f;

    // prologue: stage k-blocks 0 and 1
    #pragma unroll
    for (int r = 0; r < 8; r++)
        cpasync16(ws_s + 0 * 4224 + r * 528 + lane * 16,
                  (const char*)(proj_w + (size_t)vr[r] * H) + lane * 16);
    cpcommit();
    #pragma unroll
    for (int r = 0; r < 8; r++)
        cpasync16(ws_s + 1 * 4224 + r * 528 + lane * 16,
                  (const char*)(proj_w + (size_t)vr[r] * H) + 512 + lane * 16);
    cpcommit();

    int brow = lane >> 2;                      // vocab-local n for B frags
    int bt   = lane & 3;                       // k within 4

    #pragma unroll
    for (int i = 0; i < 8; i++) {
        const int buf = i & 1;
        if (i < 6) cpwait<1>(); else cpwait<0>();
        __syncwarp();

        const float* wsf = (const float*)(ws + buf * 4224);
        const float4* af = (const float4*)afrag + (i * 16) * 32 + lane;
        int bbase = brow * 132 + bt;

        #pragma unroll
        for (int s = 0; s < 16; s += 2) {
            float4 avA = af[s * 32];
            u32 bA0 = __float_as_uint(wsf[bbase + s * 8]);
            u32 bA1 = __float_as_uint(wsf[bbase + s * 8 + 4]);
            mma_tf32(da0, da1, da2, da3,
                     __float_as_uint(avA.x), __float_as_uint(avA.y),
                     __float_as_uint(avA.z), __float_as_uint(avA.w), bA0, bA1);
            float4 avB = af[(s + 1) * 32];
            u32 bB0 = __float_as_uint(wsf[bbase + (s + 1) * 8]);
            u32 bB1 = __float_as_uint(wsf[bbase + (s + 1) * 8 + 4]);
            mma_tf32(db0, db1, db2, db3,
                     __float_as_uint(avB.x), __float_as_uint(avB.y),
                     __float_as_uint(avB.z), __float_as_uint(avB.w), bB0, bB1);
        }

        __syncwarp();
        if (i < 6) {
            int off = (i + 2) * 512 + lane * 16;
            #pragma unroll
            for (int r = 0; r < 8; r++)
                cpasync16(ws_s + buf * 4224 + r * 528 + lane * 16,
                          (const char*)(proj_w + (size_t)vr[r] * H) + off);
            cpcommit();
        }
    }

    float d0 = da0 + db0, d1 = da1 + db1, d2 = da2 + db2, d3 = da3 + db3;

    // epilogue: D layout d0:(m=g, v=v0+2t) d1:(g, +1) d2:(g+8, 2t) d3:(g+8, +1)
    int m0 = lane >> 2;
    int m1 = m0 + 8;
    int vc0 = v0 + 2 * (lane & 3);
    int vc1 = vc0 + 1;
    bool ok0 = (vc0 < V), ok1 = (vc1 < V);
    float pb0 = proj_b[min(vc0, V - 1)];
    float pb1 = proj_b[min(vc1, V - 1)];
    float l00 = d0 + pb0, l01 = d1 + pb1;      // batch m0
    float l10 = d2 + pb0, l11 = d3 + pb1;      // batch m1
    if (ok0) { g_logits[(size_t)m0 * V + vc0] = l00;
               g_logits[(size_t)m1 * V + vc0] = l10; }
    if (ok1) { g_logits[(size_t)m0 * V + vc1] = l01;
               g_logits[(size_t)m1 * V + vc1] = l11; }

    float e0 = (ok0 ? expf(l00) : 0.f) + (ok1 ? expf(l01) : 0.f);
    float e1 = (ok0 ? expf(l10) : 0.f) + (ok1 ? expf(l11) : 0.f);
    e0 += __shfl_xor_sync(0xffffffffu, e0, 1);
    e0 += __shfl_xor_sync(0xffffffffu, e0, 2);
    e1 += __shfl_xor_sync(0xffffffffu, e1, 1);
    e1 += __shfl_xor_sync(0xffffffffu, e1, 2);
    if ((lane & 3) == 0) {
        atomicAdd(&sbin[m0], e0);
        atomicAdd(&sbin[m1], e1);
    }

    __syncthreads();
    if (tid < B) atomicAdd(&g_sum[tid], sbin[tid]);
}

// ---------------------------------------------------------------------------
// K6: out[b,t,v] = logits[b,v] - log(g_sum[b]), aligned STG.128 quads,
// streaming stores. (committed version, unchanged)
// ---------------------------------------------------------------------------
__global__ void k6_out(float* __restrict__ out) {
    int j = blockIdx.x * 256 + threadIdx.x;
    int b = blockIdx.y;
    if (j > NQ) return;
    float sub = logf(g_sum[b]);
    const float* lg = g_logits + (size_t)b * V;
    float* ob = out + (size_t)b * T * V;

    if (j < NQ) {
        float q0 = lg[4 * j + 0] - sub, q1 = lg[4 * j + 1] - sub;
        float q2 = lg[4 * j + 2] - sub, q3 = lg[4 * j + 3] - sub;
        float q4 = lg[4 * j + 4] - sub, q5 = lg[4 * j + 5] - sub;
        float q6 = lg[4 * j + 6] - sub;
        float4 v0 = make_float4(q0, q1, q2, q3);   // s=0 (r%4==0)
        float4 v3 = make_float4(q3, q4, q5, q6);   // s=3 (r%4==1)
        float4 v2 = make_float4(q2, q3, q4, q5);   // s=2 (r%4==2)
        float4 v1 = make_float4(q1, q2, q3, q4);   // s=1 (r%4==3)

        // r = b*127 + t ≡ 3b + t (mod 4); r≡c ⇔ t ≡ c + b (mod 4)
        int t0;
        t0 = (0 + b) & 3;
        #pragma unroll 4
        for (int t = t0; t < T; t += 4) __stcs((float4*)(ob + (size_t)t * V + 4 * j + 0), v0);
        t0 = (1 + b) & 3;
        #pragma unroll 4
        for (int t = t0; t < T; t += 4) __stcs((float4*)(ob + (size_t)t * V + 4 * j + 3), v3);
        t0 = (2 + b) & 3;
        #pragma unroll 4
        for (int t = t0; t < T; t += 4) __stcs((float4*)(ob + (size_t)t * V + 4 * j + 2), v2);
        t0 = (3 + b) & 3;
        #pragma unroll 4
        for (int t = t0; t < T; t += 4) __stcs((float4*)(ob + (size_t)t * V + 4 * j + 1), v1);
    } else {
        float h0 = lg[0] - sub, h1 = lg[1] - sub, h2 = lg[2] - sub;
        float e0 = lg[4 * NQ + 0] - sub, e1 = lg[4 * NQ + 1] - sub;
        float e2 = lg[4 * NQ + 2] - sub, e3 = lg[4 * NQ + 3] - sub;
        float e4 = lg[4 * NQ + 4] - sub;
        for (int t = 0; t < T; t++) {
            int c = (3 * b + t) & 3;        // r & 3
            int sshift = (4 - c) & 3;
            float* row = ob + (size_t)t * V;
            if (sshift > 0) __stcs(row + 0, h0);
            if (sshift > 1) __stcs(row + 1, h1);
            if (sshift > 2) __stcs(row + 2, h2);
            if (sshift == 0) __stcs(row + 4 * NQ + 0, e0);
            if (sshift <= 1) __stcs(row + 4 * NQ + 1, e1);
            if (sshift <= 2) __stcs(row + 4 * NQ + 2, e2);
            if (sshift <= 3) __stcs(row + 4 * NQ + 3, e3);
            __stcs(row + 4 * NQ + 4, e4);
        }
    }
}

// ---------------------------------------------------------------------------
extern "C" void kernel_launch(void* const* d_in, const int* in_sizes, int n_in,
                              void* d_out, int out_size) {
    const int*   input    = (const int*)d_in[0];
    const float* hidden   = (const float*)d_in[1];
    const float* emb      = (const float*)d_in[2];
    const float* bridge_w = (const float*)d_in[3];
    const float* bridge_b = (const float*)d_in[4];
    const float* w_ih     = (const float*)d_in[5];
    const float* w_hh     = (const float*)d_in[6];
    const float* b_ih     = (const float*)d_in[7];
    const float* b_hh     = (const float*)d_in[8];
    const float* proj_w   = (const float*)d_in[9];
    const float* proj_b   = (const float*)d_in[10];
    float* out = (float*)d_out;

    const int k4_smem = 65536 + 16 * 8448;   // afrag + staging = 200704 B
    cudaFuncSetAttribute(k4_proj, cudaFuncAttributeMaxDynamicSharedMemorySize,
                         k4_smem);

    k123_front<<<NB123, 256>>>(input, hidden, emb, bridge_w, bridge_b,
                               w_ih, w_hh, b_ih, b_hh);
    k4_proj<<<NB4, 512, k4_smem>>>(proj_w, proj_b);
    dim3 g6(50, B);
    k6_out<<<g6, 256>>>(out);
}